// round 1
// baseline (speedup 1.0000x reference)
#include <cuda_runtime.h>

#define NNODES 100000
#define FDIM   128
#define NNZ_E  1600000

// Scratch (allocations are forbidden -> device globals). 51.2 MB each.
__device__ float g_Lf[(size_t)NNODES * FDIM];
__device__ float g_Li[(size_t)NNODES * FDIM];

// ---------------------------------------------------------------------------
// Zero both scratch buffers (atomics accumulate across graph replays).
// ---------------------------------------------------------------------------
__global__ void zero_kernel() {
    size_t i = (size_t)blockIdx.x * blockDim.x + threadIdx.x;
    const size_t total = (size_t)NNODES * FDIM / 4;
    if (i < total) {
        float4 z = make_float4(0.f, 0.f, 0.f, 0.f);
        reinterpret_cast<float4*>(g_Lf)[i] = z;
        reinterpret_cast<float4*>(g_Li)[i] = z;
    }
}

// ---------------------------------------------------------------------------
// SpMM 1: g_Lf[row] += val * features[col]   (warp per edge, red.v4.f32)
// ---------------------------------------------------------------------------
__global__ void spmm1_kernel(const float* __restrict__ feat,
                             const float* __restrict__ eval,
                             const int*   __restrict__ erow,
                             const int*   __restrict__ ecol,
                             int nnz) {
    int e = blockIdx.x * (blockDim.x >> 5) + (threadIdx.x >> 5);
    if (e >= nnz) return;
    int lane = threadIdx.x & 31;
    int r = erow[e];
    int c = ecol[e];
    float v = eval[e];

    float4 x = reinterpret_cast<const float4*>(feat + (size_t)c * FDIM)[lane];
    float4 y = make_float4(v * x.x, v * x.y, v * x.z, v * x.w);
    float* dst = g_Lf + (size_t)r * FDIM + lane * 4;
    asm volatile("red.global.add.v4.f32 [%0], {%1, %2, %3, %4};"
                 :: "l"(dst), "f"(y.x), "f"(y.y), "f"(y.z), "f"(y.w)
                 : "memory");
}

// ---------------------------------------------------------------------------
// SpMM 2: g_Li[row] += val * (g_Lf[col] * features[col])   (fused gather-mul)
// ---------------------------------------------------------------------------
__global__ void spmm2_kernel(const float* __restrict__ feat,
                             const float* __restrict__ eval,
                             const int*   __restrict__ erow,
                             const int*   __restrict__ ecol,
                             int nnz) {
    int e = blockIdx.x * (blockDim.x >> 5) + (threadIdx.x >> 5);
    if (e >= nnz) return;
    int lane = threadIdx.x & 31;
    int r = erow[e];
    int c = ecol[e];
    float v = eval[e];

    float4 lf = reinterpret_cast<const float4*>(g_Lf + (size_t)c * FDIM)[lane];
    float4 ft = reinterpret_cast<const float4*>(feat + (size_t)c * FDIM)[lane];
    float4 y  = make_float4(v * lf.x * ft.x, v * lf.y * ft.y,
                            v * lf.z * ft.z, v * lf.w * ft.w);
    float* dst = g_Li + (size_t)r * FDIM + lane * 4;
    asm volatile("red.global.add.v4.f32 [%0], {%1, %2, %3, %4};"
                 :: "l"(dst), "f"(y.x), "f"(y.y), "f"(y.z), "f"(y.w)
                 : "memory");
}

// ---------------------------------------------------------------------------
// Fused GEMM epilogue:
//   out = [Lf+feat ; Li] (N x 256) @ [W1 ; W2] (256 x 128) + (b1 + b2)
// Block: 512 threads = 16 warps, 4 rows per warp -> 64 rows per block.
// Each lane owns 4 output columns; 4x4 register accumulator tile.
// W lives in smem (131072 B), per-warp A staging in smem (65536 B).
// ---------------------------------------------------------------------------
__global__ __launch_bounds__(512, 1)
void gemm_kernel(const float* __restrict__ feat,
                 const float* __restrict__ W1,
                 const float* __restrict__ b1,
                 const float* __restrict__ W2,
                 const float* __restrict__ b2,
                 float* __restrict__ out) {
    extern __shared__ float sm[];
    float* Ws   = sm;                 // 256*128 floats
    float* bsum = sm + 256 * 128;     // 128 floats
    float* abuf = bsum + 128;         // 16 warps * 4 rows * 256 floats

    const int tid  = threadIdx.x;
    const int warp = tid >> 5;
    const int lane = tid & 31;

    // Stage W = [W1 ; W2] into smem (each is 4096 float4).
    {
        float4*       d1 = reinterpret_cast<float4*>(Ws);
        const float4* s1 = reinterpret_cast<const float4*>(W1);
        const float4* s2 = reinterpret_cast<const float4*>(W2);
        #pragma unroll
        for (int i = 0; i < 8; i++) {
            int idx = tid + i * 512;
            d1[idx]        = s1[idx];
            d1[idx + 4096] = s2[idx];
        }
    }
    if (tid < 128) bsum[tid] = b1[tid] + b2[tid];
    __syncthreads();

    const int row0 = blockIdx.x * 64 + warp * 4;
    float* ab = abuf + warp * (4 * 256);

    // Stage A rows: [Lf+feat (128) ; Li (128)] per row.
    #pragma unroll
    for (int r = 0; r < 4; r++) {
        int row = row0 + r;
        float4 s, li;
        if (row < NNODES) {
            float4 lf = reinterpret_cast<const float4*>(g_Lf + (size_t)row * FDIM)[lane];
            float4 ft = reinterpret_cast<const float4*>(feat + (size_t)row * FDIM)[lane];
            s  = make_float4(lf.x + ft.x, lf.y + ft.y, lf.z + ft.z, lf.w + ft.w);
            li = reinterpret_cast<const float4*>(g_Li + (size_t)row * FDIM)[lane];
        } else {
            s  = make_float4(0.f, 0.f, 0.f, 0.f);
            li = s;
        }
        reinterpret_cast<float4*>(ab + r * 256)[lane]       = s;
        reinterpret_cast<float4*>(ab + r * 256 + 128)[lane] = li;
    }
    __syncwarp();

    float acc[4][4];
    #pragma unroll
    for (int r = 0; r < 4; r++)
        #pragma unroll
        for (int c = 0; c < 4; c++) acc[r][c] = 0.f;

    // Main loop: 4 k-steps per iteration. 8 LDS.128 + 64 FFMA per iter.
    #pragma unroll 2
    for (int k4 = 0; k4 < 256; k4 += 4) {
        float4 w[4];
        #pragma unroll
        for (int i = 0; i < 4; i++)
            w[i] = reinterpret_cast<const float4*>(Ws + (k4 + i) * 128)[lane];

        #pragma unroll
        for (int r = 0; r < 4; r++) {
            float4 a = *reinterpret_cast<const float4*>(ab + r * 256 + k4);
            acc[r][0] = fmaf(a.x, w[0].x, acc[r][0]);
            acc[r][1] = fmaf(a.x, w[0].y, acc[r][1]);
            acc[r][2] = fmaf(a.x, w[0].z, acc[r][2]);
            acc[r][3] = fmaf(a.x, w[0].w, acc[r][3]);

            acc[r][0] = fmaf(a.y, w[1].x, acc[r][0]);
            acc[r][1] = fmaf(a.y, w[1].y, acc[r][1]);
            acc[r][2] = fmaf(a.y, w[1].z, acc[r][2]);
            acc[r][3] = fmaf(a.y, w[1].w, acc[r][3]);

            acc[r][0] = fmaf(a.z, w[2].x, acc[r][0]);
            acc[r][1] = fmaf(a.z, w[2].y, acc[r][1]);
            acc[r][2] = fmaf(a.z, w[2].z, acc[r][2]);
            acc[r][3] = fmaf(a.z, w[2].w, acc[r][3]);

            acc[r][0] = fmaf(a.w, w[3].x, acc[r][0]);
            acc[r][1] = fmaf(a.w, w[3].y, acc[r][1]);
            acc[r][2] = fmaf(a.w, w[3].z, acc[r][2]);
            acc[r][3] = fmaf(a.w, w[3].w, acc[r][3]);
        }
    }

    // Epilogue: add fused bias, store float4 per lane per row.
    float4 bb = reinterpret_cast<const float4*>(bsum)[lane];
    #pragma unroll
    for (int r = 0; r < 4; r++) {
        int row = row0 + r;
        if (row < NNODES) {
            float4 o = make_float4(acc[r][0] + bb.x, acc[r][1] + bb.y,
                                   acc[r][2] + bb.z, acc[r][3] + bb.w);
            reinterpret_cast<float4*>(out + (size_t)row * FDIM)[lane] = o;
        }
    }
}

// ---------------------------------------------------------------------------
extern "C" void kernel_launch(void* const* d_in, const int* in_sizes, int n_in,
                              void* d_out, int out_size) {
    const float* feat = (const float*)d_in[0];   // (N, 128) f32
    const float* eval = (const float*)d_in[1];   // (NNZ,)   f32
    const float* W1   = (const float*)d_in[2];   // (128,128) f32
    const float* b1   = (const float*)d_in[3];   // (128,)   f32
    const float* W2   = (const float*)d_in[4];   // (128,128) f32
    const float* b2   = (const float*)d_in[5];   // (128,)   f32
    const int*   erow = (const int*)d_in[6];     // (NNZ,)   i32
    const int*   ecol = (const int*)d_in[7];     // (NNZ,)   i32
    float*       out  = (float*)d_out;

    const int nnz = in_sizes[1];

    // 1) zero scratch
    {
        const size_t total = (size_t)NNODES * FDIM / 4;
        int blocks = (int)((total + 255) / 256);
        zero_kernel<<<blocks, 256>>>();
    }

    // 2) Lf = A @ features
    {
        int edges_per_block = 256 / 32;
        int blocks = (nnz + edges_per_block - 1) / edges_per_block;
        spmm1_kernel<<<blocks, 256>>>(feat, eval, erow, ecol, nnz);
    }

    // 3) Li = A @ (Lf * features)
    {
        int edges_per_block = 256 / 32;
        int blocks = (nnz + edges_per_block - 1) / edges_per_block;
        spmm2_kernel<<<blocks, 256>>>(feat, eval, erow, ecol, nnz);
    }

    // 4) out = [Lf+feat ; Li] @ [W1;W2] + (b1+b2)
    {
        const int smem_bytes = (256 * 128 + 128 + 16 * 4 * 256) * sizeof(float);
        cudaFuncSetAttribute(gemm_kernel,
                             cudaFuncAttributeMaxDynamicSharedMemorySize,
                             smem_bytes);
        int blocks = (NNODES + 63) / 64;
        gemm_kernel<<<blocks, 512, smem_bytes>>>(feat, W1, b1, W2, b2, out);
    }
}

// round 2
// speedup vs baseline: 1.3128x; 1.3128x over previous
#include <cuda_runtime.h>

#define NNODES 100000
#define FDIM   128

// ---- device-global scratch (allocations forbidden) ----
__device__ float g_LfP[(size_t)NNODES * FDIM];   // Lf + feat   (GEMM A, left half)
__device__ float g_P  [(size_t)NNODES * FDIM];   // Lf * feat   (spmm2 input)
__device__ float g_Li [(size_t)NNODES * FDIM];   // A @ P       (GEMM A, right half)
__device__ int   g_rowcnt[NNODES];
__device__ int   g_rowptr[NNODES + 1];
__device__ int   g_rowcur[NNODES];
__device__ int   g_csr_col[1600000 + 1024];
__device__ float g_csr_val[1600000 + 1024];

// ---------------------------------------------------------------------------
// CSR build: zero counts -> histogram -> scan -> scatter
// ---------------------------------------------------------------------------
__global__ void zero_counts_kernel() {
    int i = blockIdx.x * blockDim.x + threadIdx.x;
    if (i < NNODES) g_rowcnt[i] = 0;
}

__global__ void hist_kernel(const int* __restrict__ erow, int nnz) {
    int i = blockIdx.x * blockDim.x + threadIdx.x;
    if (i < nnz) atomicAdd(&g_rowcnt[erow[i]], 1);
}

// Single-block exclusive scan over 100k counts (chunked + Hillis-Steele).
__global__ __launch_bounds__(1024, 1)
void scan_kernel() {
    __shared__ int s[1024];
    const int T = 1024;
    const int n = NNODES;
    int tid = threadIdx.x;
    int chunk = (n + T - 1) / T;
    int start = tid * chunk;
    int end   = min(start + chunk, n);

    int sum = 0;
    for (int i = start; i < end; i++) sum += g_rowcnt[i];
    s[tid] = sum;
    __syncthreads();
    // inclusive scan
    for (int off = 1; off < T; off <<= 1) {
        int v = (tid >= off) ? s[tid - off] : 0;
        __syncthreads();
        s[tid] += v;
        __syncthreads();
    }
    int excl = (tid == 0) ? 0 : s[tid - 1];
    for (int i = start; i < end; i++) {
        int c = g_rowcnt[i];
        g_rowptr[i] = excl;
        g_rowcur[i] = excl;
        excl += c;
    }
    if (tid == T - 1) g_rowptr[n] = excl;
}

__global__ void scatter_kernel(const float* __restrict__ eval,
                               const int*   __restrict__ erow,
                               const int*   __restrict__ ecol,
                               int nnz) {
    int i = blockIdx.x * blockDim.x + threadIdx.x;
    if (i < nnz) {
        int r   = erow[i];
        int pos = atomicAdd(&g_rowcur[r], 1);
        g_csr_col[pos] = ecol[i];
        g_csr_val[pos] = eval[i];
    }
}

// ---------------------------------------------------------------------------
// SpMM-CSR, warp per row. Accumulate in registers, plain stores.
//   Pass 1: acc = sum_e val*feat[col];  write LfP = acc + feat[row],
//                                             P   = acc * feat[row]
//   Pass 2: acc = sum_e val*P[col];     write Li = acc
// ---------------------------------------------------------------------------
__global__ __launch_bounds__(256)
void spmm1_csr_kernel(const float* __restrict__ feat) {
    int row = blockIdx.x * (blockDim.x >> 5) + (threadIdx.x >> 5);
    if (row >= NNODES) return;
    int lane = threadIdx.x & 31;
    int beg = g_rowptr[row];
    int end = g_rowptr[row + 1];

    float4 acc = make_float4(0.f, 0.f, 0.f, 0.f);
    for (int base = beg; base < end; base += 32) {
        int cnt = min(32, end - base);
        int   mycol = 0;
        float myval = 0.f;
        if (lane < cnt) {
            mycol = g_csr_col[base + lane];
            myval = g_csr_val[base + lane];
        }
        #pragma unroll 4
        for (int j = 0; j < cnt; j++) {
            int   c = __shfl_sync(0xffffffffu, mycol, j);
            float v = __shfl_sync(0xffffffffu, myval, j);
            float4 x = reinterpret_cast<const float4*>(feat + (size_t)c * FDIM)[lane];
            acc.x = fmaf(v, x.x, acc.x);
            acc.y = fmaf(v, x.y, acc.y);
            acc.z = fmaf(v, x.z, acc.z);
            acc.w = fmaf(v, x.w, acc.w);
        }
    }
    float4 ft = reinterpret_cast<const float4*>(feat + (size_t)row * FDIM)[lane];
    float4 lp = make_float4(acc.x + ft.x, acc.y + ft.y, acc.z + ft.z, acc.w + ft.w);
    float4 pp = make_float4(acc.x * ft.x, acc.y * ft.y, acc.z * ft.z, acc.w * ft.w);
    reinterpret_cast<float4*>(g_LfP + (size_t)row * FDIM)[lane] = lp;
    reinterpret_cast<float4*>(g_P   + (size_t)row * FDIM)[lane] = pp;
}

__global__ __launch_bounds__(256)
void spmm2_csr_kernel() {
    int row = blockIdx.x * (blockDim.x >> 5) + (threadIdx.x >> 5);
    if (row >= NNODES) return;
    int lane = threadIdx.x & 31;
    int beg = g_rowptr[row];
    int end = g_rowptr[row + 1];

    float4 acc = make_float4(0.f, 0.f, 0.f, 0.f);
    for (int base = beg; base < end; base += 32) {
        int cnt = min(32, end - base);
        int   mycol = 0;
        float myval = 0.f;
        if (lane < cnt) {
            mycol = g_csr_col[base + lane];
            myval = g_csr_val[base + lane];
        }
        #pragma unroll 4
        for (int j = 0; j < cnt; j++) {
            int   c = __shfl_sync(0xffffffffu, mycol, j);
            float v = __shfl_sync(0xffffffffu, myval, j);
            float4 x = reinterpret_cast<const float4*>(g_P + (size_t)c * FDIM)[lane];
            acc.x = fmaf(v, x.x, acc.x);
            acc.y = fmaf(v, x.y, acc.y);
            acc.z = fmaf(v, x.z, acc.z);
            acc.w = fmaf(v, x.w, acc.w);
        }
    }
    reinterpret_cast<float4*>(g_Li + (size_t)row * FDIM)[lane] = acc;
}

// ---------------------------------------------------------------------------
// Fused GEMM:  out = [LfP ; Li] (N x 256) @ [W1 ; W2] (256 x 128) + (b1+b2)
// 512 thr = 16 warps, 4 rows/warp, 4x4 register tile per lane.
// ---------------------------------------------------------------------------
__global__ __launch_bounds__(512, 1)
void gemm_kernel(const float* __restrict__ W1,
                 const float* __restrict__ b1,
                 const float* __restrict__ W2,
                 const float* __restrict__ b2,
                 float* __restrict__ out) {
    extern __shared__ float sm[];
    float* Ws   = sm;                 // 256*128
    float* bsum = sm + 256 * 128;     // 128
    float* abuf = bsum + 128;         // 16 * 4 * 256

    const int tid  = threadIdx.x;
    const int warp = tid >> 5;
    const int lane = tid & 31;

    {
        float4*       d1 = reinterpret_cast<float4*>(Ws);
        const float4* s1 = reinterpret_cast<const float4*>(W1);
        const float4* s2 = reinterpret_cast<const float4*>(W2);
        #pragma unroll
        for (int i = 0; i < 8; i++) {
            int idx = tid + i * 512;
            d1[idx]        = s1[idx];
            d1[idx + 4096] = s2[idx];
        }
    }
    if (tid < 128) bsum[tid] = b1[tid] + b2[tid];
    __syncthreads();

    const int row0 = blockIdx.x * 64 + warp * 4;
    float* ab = abuf + warp * (4 * 256);

    #pragma unroll
    for (int r = 0; r < 4; r++) {
        int row = row0 + r;
        float4 s, li;
        if (row < NNODES) {
            s  = reinterpret_cast<const float4*>(g_LfP + (size_t)row * FDIM)[lane];
            li = reinterpret_cast<const float4*>(g_Li  + (size_t)row * FDIM)[lane];
        } else {
            s  = make_float4(0.f, 0.f, 0.f, 0.f);
            li = s;
        }
        reinterpret_cast<float4*>(ab + r * 256)[lane]       = s;
        reinterpret_cast<float4*>(ab + r * 256 + 128)[lane] = li;
    }
    __syncwarp();

    float acc[4][4];
    #pragma unroll
    for (int r = 0; r < 4; r++)
        #pragma unroll
        for (int c = 0; c < 4; c++) acc[r][c] = 0.f;

    #pragma unroll 2
    for (int k4 = 0; k4 < 256; k4 += 4) {
        float4 w[4];
        #pragma unroll
        for (int i = 0; i < 4; i++)
            w[i] = reinterpret_cast<const float4*>(Ws + (k4 + i) * 128)[lane];

        #pragma unroll
        for (int r = 0; r < 4; r++) {
            float4 a = *reinterpret_cast<const float4*>(ab + r * 256 + k4);
            acc[r][0] = fmaf(a.x, w[0].x, acc[r][0]);
            acc[r][1] = fmaf(a.x, w[0].y, acc[r][1]);
            acc[r][2] = fmaf(a.x, w[0].z, acc[r][2]);
            acc[r][3] = fmaf(a.x, w[0].w, acc[r][3]);

            acc[r][0] = fmaf(a.y, w[1].x, acc[r][0]);
            acc[r][1] = fmaf(a.y, w[1].y, acc[r][1]);
            acc[r][2] = fmaf(a.y, w[1].z, acc[r][2]);
            acc[r][3] = fmaf(a.y, w[1].w, acc[r][3]);

            acc[r][0] = fmaf(a.z, w[2].x, acc[r][0]);
            acc[r][1] = fmaf(a.z, w[2].y, acc[r][1]);
            acc[r][2] = fmaf(a.z, w[2].z, acc[r][2]);
            acc[r][3] = fmaf(a.z, w[2].w, acc[r][3]);

            acc[r][0] = fmaf(a.w, w[3].x, acc[r][0]);
            acc[r][1] = fmaf(a.w, w[3].y, acc[r][1]);
            acc[r][2] = fmaf(a.w, w[3].z, acc[r][2]);
            acc[r][3] = fmaf(a.w, w[3].w, acc[r][3]);
        }
    }

    float4 bb = reinterpret_cast<const float4*>(bsum)[lane];
    #pragma unroll
    for (int r = 0; r < 4; r++) {
        int row = row0 + r;
        if (row < NNODES) {
            float4 o = make_float4(acc[r][0] + bb.x, acc[r][1] + bb.y,
                                   acc[r][2] + bb.z, acc[r][3] + bb.w);
            reinterpret_cast<float4*>(out + (size_t)row * FDIM)[lane] = o;
        }
    }
}

// ---------------------------------------------------------------------------
extern "C" void kernel_launch(void* const* d_in, const int* in_sizes, int n_in,
                              void* d_out, int out_size) {
    const float* feat = (const float*)d_in[0];
    const float* eval = (const float*)d_in[1];
    const float* W1   = (const float*)d_in[2];
    const float* b1   = (const float*)d_in[3];
    const float* W2   = (const float*)d_in[4];
    const float* b2   = (const float*)d_in[5];
    const int*   erow = (const int*)d_in[6];
    const int*   ecol = (const int*)d_in[7];
    float*       out  = (float*)d_out;

    const int nnz = in_sizes[1];

    // CSR build
    zero_counts_kernel<<<(NNODES + 255) / 256, 256>>>();
    hist_kernel<<<(nnz + 255) / 256, 256>>>(erow, nnz);
    scan_kernel<<<1, 1024>>>();
    scatter_kernel<<<(nnz + 255) / 256, 256>>>(eval, erow, ecol, nnz);

    // SpMM passes (warp per row)
    {
        int blocks = (NNODES + 7) / 8;   // 8 warps per 256-thread block
        spmm1_csr_kernel<<<blocks, 256>>>(feat);
        spmm2_csr_kernel<<<blocks, 256>>>();
    }

    // GEMM
    {
        const int smem_bytes = (256 * 128 + 128 + 16 * 4 * 256) * sizeof(float);
        cudaFuncSetAttribute(gemm_kernel,
                             cudaFuncAttributeMaxDynamicSharedMemorySize,
                             smem_bytes);
        int blocks = (NNODES + 63) / 64;
        gemm_kernel<<<blocks, 512, smem_bytes>>>(W1, b1, W2, b2, out);
    }
}

// round 3
// speedup vs baseline: 1.3811x; 1.0520x over previous
#include <cuda_runtime.h>

#define NNODES 100000
#define FDIM   128

// ---- device-global scratch (allocations forbidden) ----
__device__ float g_LfP[(size_t)NNODES * FDIM];   // Lf + feat   (GEMM A, left half)
__device__ float g_P  [(size_t)NNODES * FDIM];   // Lf * feat   (spmm2 input)
__device__ float g_Li [(size_t)NNODES * FDIM];   // A @ P       (GEMM A, right half)
__device__ int   g_rowcnt[NNODES];
__device__ int   g_rowptr[NNODES + 1];
__device__ int   g_rowcur[NNODES];
__device__ int2  g_csr[1600000 + 1024];          // (col, float_bits(val)) packed

// ---------------------------------------------------------------------------
// CSR build: zero counts -> histogram -> scan -> scatter
// ---------------------------------------------------------------------------
__global__ void zero_counts_kernel() {
    int i = blockIdx.x * blockDim.x + threadIdx.x;
    if (i < NNODES) g_rowcnt[i] = 0;
}

__global__ void hist_kernel(const int* __restrict__ erow, int nnz) {
    int i = blockIdx.x * blockDim.x + threadIdx.x;
    if (i < nnz) atomicAdd(&g_rowcnt[erow[i]], 1);
}

// Single-block exclusive scan over 100k counts (chunked + Hillis-Steele).
__global__ __launch_bounds__(1024, 1)
void scan_kernel() {
    __shared__ int s[1024];
    const int T = 1024;
    const int n = NNODES;
    int tid = threadIdx.x;
    int chunk = (n + T - 1) / T;
    int start = tid * chunk;
    int end   = min(start + chunk, n);

    int sum = 0;
    for (int i = start; i < end; i++) sum += g_rowcnt[i];
    s[tid] = sum;
    __syncthreads();
    for (int off = 1; off < T; off <<= 1) {
        int v = (tid >= off) ? s[tid - off] : 0;
        __syncthreads();
        s[tid] += v;
        __syncthreads();
    }
    int excl = (tid == 0) ? 0 : s[tid - 1];
    for (int i = start; i < end; i++) {
        int c = g_rowcnt[i];
        g_rowptr[i] = excl;
        g_rowcur[i] = excl;
        excl += c;
    }
    if (tid == T - 1) g_rowptr[n] = excl;
}

__global__ void scatter_kernel(const float* __restrict__ eval,
                               const int*   __restrict__ erow,
                               const int*   __restrict__ ecol,
                               int nnz) {
    int i = blockIdx.x * blockDim.x + threadIdx.x;
    if (i < nnz) {
        int r   = erow[i];
        int pos = atomicAdd(&g_rowcur[r], 1);
        g_csr[pos] = make_int2(ecol[i], __float_as_int(eval[i]));
    }
}

// ---------------------------------------------------------------------------
// SpMM-CSR, warp per row. Register accumulate, plain stores.
// ---------------------------------------------------------------------------
__global__ __launch_bounds__(256)
void spmm1_csr_kernel(const float* __restrict__ feat) {
    int row = blockIdx.x * (blockDim.x >> 5) + (threadIdx.x >> 5);
    if (row >= NNODES) return;
    int lane = threadIdx.x & 31;
    int beg = g_rowptr[row];
    int end = g_rowptr[row + 1];

    float4 acc = make_float4(0.f, 0.f, 0.f, 0.f);
    for (int base = beg; base < end; base += 32) {
        int cnt = min(32, end - base);
        int   mycol = 0;
        float myval = 0.f;
        if (lane < cnt) {
            int2 e = g_csr[base + lane];
            mycol = e.x;
            myval = __int_as_float(e.y);
        }
        #pragma unroll 4
        for (int j = 0; j < cnt; j++) {
            int   c = __shfl_sync(0xffffffffu, mycol, j);
            float v = __shfl_sync(0xffffffffu, myval, j);
            float4 x = reinterpret_cast<const float4*>(feat + (size_t)c * FDIM)[lane];
            acc.x = fmaf(v, x.x, acc.x);
            acc.y = fmaf(v, x.y, acc.y);
            acc.z = fmaf(v, x.z, acc.z);
            acc.w = fmaf(v, x.w, acc.w);
        }
    }
    float4 ft = reinterpret_cast<const float4*>(feat + (size_t)row * FDIM)[lane];
    float4 lp = make_float4(acc.x + ft.x, acc.y + ft.y, acc.z + ft.z, acc.w + ft.w);
    float4 pp = make_float4(acc.x * ft.x, acc.y * ft.y, acc.z * ft.z, acc.w * ft.w);
    reinterpret_cast<float4*>(g_LfP + (size_t)row * FDIM)[lane] = lp;
    reinterpret_cast<float4*>(g_P   + (size_t)row * FDIM)[lane] = pp;
}

__global__ __launch_bounds__(256)
void spmm2_csr_kernel() {
    int row = blockIdx.x * (blockDim.x >> 5) + (threadIdx.x >> 5);
    if (row >= NNODES) return;
    int lane = threadIdx.x & 31;
    int beg = g_rowptr[row];
    int end = g_rowptr[row + 1];

    float4 acc = make_float4(0.f, 0.f, 0.f, 0.f);
    for (int base = beg; base < end; base += 32) {
        int cnt = min(32, end - base);
        int   mycol = 0;
        float myval = 0.f;
        if (lane < cnt) {
            int2 e = g_csr[base + lane];
            mycol = e.x;
            myval = __int_as_float(e.y);
        }
        #pragma unroll 4
        for (int j = 0; j < cnt; j++) {
            int   c = __shfl_sync(0xffffffffu, mycol, j);
            float v = __shfl_sync(0xffffffffu, myval, j);
            float4 x = reinterpret_cast<const float4*>(g_P + (size_t)c * FDIM)[lane];
            acc.x = fmaf(v, x.x, acc.x);
            acc.y = fmaf(v, x.y, acc.y);
            acc.z = fmaf(v, x.z, acc.z);
            acc.w = fmaf(v, x.w, acc.w);
        }
    }
    reinterpret_cast<float4*>(g_Li + (size_t)row * FDIM)[lane] = acc;
}

// ---------------------------------------------------------------------------
// Fused GEMM via packed fp32 (fma.rn.f32x2):
//   out = [LfP ; Li] (N x 256) @ [W1 ; W2] (256 x 128) + (b1+b2)
// 256 thr = 8 warps, 8 rows/warp -> 64 rows/block. Lane owns 4 cols as
// 2 packed f32x2 accumulators per row.
// ---------------------------------------------------------------------------
__device__ __forceinline__ unsigned long long dup_f32x2(float a) {
    unsigned long long d;
    asm("mov.b64 %0, {%1, %1};" : "=l"(d) : "f"(a));
    return d;
}
__device__ __forceinline__ void fma2(unsigned long long& acc,
                                     unsigned long long a,
                                     unsigned long long b) {
    asm("fma.rn.f32x2 %0, %1, %2, %0;" : "+l"(acc) : "l"(a), "l"(b));
}

__global__ __launch_bounds__(256, 1)
void gemm_kernel(const float* __restrict__ W1,
                 const float* __restrict__ b1,
                 const float* __restrict__ W2,
                 const float* __restrict__ b2,
                 float* __restrict__ out) {
    extern __shared__ float sm[];
    float* Ws   = sm;                 // 256*128 = 32768 floats
    float* bsum = sm + 32768;         // 128
    float* abuf = bsum + 128;         // 8 warps * 8 rows * 256 = 16384 floats

    const int tid  = threadIdx.x;
    const int warp = tid >> 5;
    const int lane = tid & 31;

    // Stage W = [W1 ; W2] (each 4096 float4; 256 threads x 16 iters)
    {
        float4*       d  = reinterpret_cast<float4*>(Ws);
        const float4* s1 = reinterpret_cast<const float4*>(W1);
        const float4* s2 = reinterpret_cast<const float4*>(W2);
        #pragma unroll
        for (int i = 0; i < 16; i++) {
            int idx = tid + i * 256;
            d[idx]        = s1[idx];
            d[idx + 4096] = s2[idx];
        }
    }
    if (tid < 128) bsum[tid] = b1[tid] + b2[tid];
    __syncthreads();

    const int row0 = blockIdx.x * 64 + warp * 8;
    float* ab = abuf + warp * (8 * 256);

    // Stage A rows: [LfP (128) ; Li (128)] per row.
    #pragma unroll
    for (int r = 0; r < 8; r++) {
        int row = row0 + r;
        float4 s, li;
        if (row < NNODES) {
            s  = reinterpret_cast<const float4*>(g_LfP + (size_t)row * FDIM)[lane];
            li = reinterpret_cast<const float4*>(g_Li  + (size_t)row * FDIM)[lane];
        } else {
            s  = make_float4(0.f, 0.f, 0.f, 0.f);
            li = s;
        }
        reinterpret_cast<float4*>(ab + r * 256)[lane]       = s;
        reinterpret_cast<float4*>(ab + r * 256 + 128)[lane] = li;
    }
    __syncwarp();

    unsigned long long acc[8][2];
    #pragma unroll
    for (int r = 0; r < 8; r++) { acc[r][0] = 0ull; acc[r][1] = 0ull; }

    // Main loop: per iter 12 LDS.128 + 64 FFMA2 + 32 dup-mov per warp.
    #pragma unroll 2
    for (int k4 = 0; k4 < 256; k4 += 4) {
        ulonglong2 w[4];   // w[i].x = cols(c0,c1), w[i].y = cols(c2,c3)
        #pragma unroll
        for (int i = 0; i < 4; i++)
            w[i] = reinterpret_cast<const ulonglong2*>(Ws + (k4 + i) * 128)[lane];

        #pragma unroll
        for (int r = 0; r < 8; r++) {
            float4 a = *reinterpret_cast<const float4*>(ab + r * 256 + k4);
            unsigned long long a0 = dup_f32x2(a.x);
            unsigned long long a1 = dup_f32x2(a.y);
            unsigned long long a2 = dup_f32x2(a.z);
            unsigned long long a3 = dup_f32x2(a.w);
            fma2(acc[r][0], a0, w[0].x);  fma2(acc[r][1], a0, w[0].y);
            fma2(acc[r][0], a1, w[1].x);  fma2(acc[r][1], a1, w[1].y);
            fma2(acc[r][0], a2, w[2].x);  fma2(acc[r][1], a2, w[2].y);
            fma2(acc[r][0], a3, w[3].x);  fma2(acc[r][1], a3, w[3].y);
        }
    }

    float4 bb = reinterpret_cast<const float4*>(bsum)[lane];
    #pragma unroll
    for (int r = 0; r < 8; r++) {
        int row = row0 + r;
        if (row < NNODES) {
            float c0, c1, c2, c3;
            asm("mov.b64 {%0, %1}, %2;" : "=f"(c0), "=f"(c1) : "l"(acc[r][0]));
            asm("mov.b64 {%0, %1}, %2;" : "=f"(c2), "=f"(c3) : "l"(acc[r][1]));
            float4 o = make_float4(c0 + bb.x, c1 + bb.y, c2 + bb.z, c3 + bb.w);
            reinterpret_cast<float4*>(out + (size_t)row * FDIM)[lane] = o;
        }
    }
}

// ---------------------------------------------------------------------------
extern "C" void kernel_launch(void* const* d_in, const int* in_sizes, int n_in,
                              void* d_out, int out_size) {
    const float* feat = (const float*)d_in[0];
    const float* eval = (const float*)d_in[1];
    const float* W1   = (const float*)d_in[2];
    const float* b1   = (const float*)d_in[3];
    const float* W2   = (const float*)d_in[4];
    const float* b2   = (const float*)d_in[5];
    const int*   erow = (const int*)d_in[6];
    const int*   ecol = (const int*)d_in[7];
    float*       out  = (float*)d_out;

    const int nnz = in_sizes[1];

    // CSR build
    zero_counts_kernel<<<(NNODES + 255) / 256, 256>>>();
    hist_kernel<<<(nnz + 255) / 256, 256>>>(erow, nnz);
    scan_kernel<<<1, 1024>>>();
    scatter_kernel<<<(nnz + 255) / 256, 256>>>(eval, erow, ecol, nnz);

    // SpMM passes (warp per row)
    {
        int blocks = (NNODES + 7) / 8;
        spmm1_csr_kernel<<<blocks, 256>>>(feat);
        spmm2_csr_kernel<<<blocks, 256>>>();
    }

    // GEMM (packed f32x2)
    {
        const int smem_bytes = (32768 + 128 + 16384) * sizeof(float);
        cudaFuncSetAttribute(gemm_kernel,
                             cudaFuncAttributeMaxDynamicSharedMemorySize,
                             smem_bytes);
        int blocks = (NNODES + 63) / 64;
        gemm_kernel<<<blocks, 256, smem_bytes>>>(W1, b1, W2, b2, out);
    }
}

// round 5
// speedup vs baseline: 1.6611x; 1.2027x over previous
#include <cuda_runtime.h>
#include <cstdint>

#define NNODES 100000
#define FDIM   128

// ---- device-global scratch (allocations forbidden) ----
__device__ float g_LfP[(size_t)NNODES * FDIM];   // Lf + feat   (GEMM A, k 0..127)
__device__ float g_P  [(size_t)NNODES * FDIM];   // Lf * feat   (spmm2 input)
__device__ float g_Li [(size_t)NNODES * FDIM];   // A @ P       (GEMM A, k 128..255)
__device__ int   g_rowcnt[NNODES];
__device__ int   g_rowptr[NNODES + 1];
__device__ int   g_rowcur[NNODES];
__device__ int2  g_csr[1600000 + 1024];          // (col, float_bits(val)) packed

// ---------------------------------------------------------------------------
// CSR build: zero counts -> histogram -> scan -> scatter
// ---------------------------------------------------------------------------
__global__ void zero_counts_kernel() {
    int i = blockIdx.x * blockDim.x + threadIdx.x;
    if (i < NNODES) g_rowcnt[i] = 0;
}

__global__ void hist_kernel(const int* __restrict__ erow, int nnz) {
    int i = blockIdx.x * blockDim.x + threadIdx.x;
    if (i < nnz) atomicAdd(&g_rowcnt[erow[i]], 1);
}

__global__ __launch_bounds__(1024, 1)
void scan_kernel() {
    __shared__ int s[1024];
    const int T = 1024;
    const int n = NNODES;
    int tid = threadIdx.x;
    int chunk = (n + T - 1) / T;
    int start = tid * chunk;
    int end   = min(start + chunk, n);

    int sum = 0;
    for (int i = start; i < end; i++) sum += g_rowcnt[i];
    s[tid] = sum;
    __syncthreads();
    for (int off = 1; off < T; off <<= 1) {
        int v = (tid >= off) ? s[tid - off] : 0;
        __syncthreads();
        s[tid] += v;
        __syncthreads();
    }
    int excl = (tid == 0) ? 0 : s[tid - 1];
    for (int i = start; i < end; i++) {
        int c = g_rowcnt[i];
        g_rowptr[i] = excl;
        g_rowcur[i] = excl;
        excl += c;
    }
    if (tid == T - 1) g_rowptr[n] = excl;
}

__global__ void scatter_kernel(const float* __restrict__ eval,
                               const int*   __restrict__ erow,
                               const int*   __restrict__ ecol,
                               int nnz) {
    int i = blockIdx.x * blockDim.x + threadIdx.x;
    if (i < nnz) {
        int r   = erow[i];
        int pos = atomicAdd(&g_rowcur[r], 1);
        g_csr[pos] = make_int2(ecol[i], __float_as_int(eval[i]));
    }
}

// ---------------------------------------------------------------------------
// SpMM-CSR, warp per row. Register accumulate, plain stores.
// ---------------------------------------------------------------------------
__global__ __launch_bounds__(256)
void spmm1_csr_kernel(const float* __restrict__ feat) {
    int row = blockIdx.x * (blockDim.x >> 5) + (threadIdx.x >> 5);
    if (row >= NNODES) return;
    int lane = threadIdx.x & 31;
    int beg = g_rowptr[row];
    int end = g_rowptr[row + 1];

    float4 acc = make_float4(0.f, 0.f, 0.f, 0.f);
    for (int base = beg; base < end; base += 32) {
        int cnt = min(32, end - base);
        int   mycol = 0;
        float myval = 0.f;
        if (lane < cnt) {
            int2 e = g_csr[base + lane];
            mycol = e.x;
            myval = __int_as_float(e.y);
        }
        #pragma unroll 4
        for (int j = 0; j < cnt; j++) {
            int   c = __shfl_sync(0xffffffffu, mycol, j);
            float v = __shfl_sync(0xffffffffu, myval, j);
            float4 x = reinterpret_cast<const float4*>(feat + (size_t)c * FDIM)[lane];
            acc.x = fmaf(v, x.x, acc.x);
            acc.y = fmaf(v, x.y, acc.y);
            acc.z = fmaf(v, x.z, acc.z);
            acc.w = fmaf(v, x.w, acc.w);
        }
    }
    float4 ft = reinterpret_cast<const float4*>(feat + (size_t)row * FDIM)[lane];
    float4 lp = make_float4(acc.x + ft.x, acc.y + ft.y, acc.z + ft.z, acc.w + ft.w);
    float4 pp = make_float4(acc.x * ft.x, acc.y * ft.y, acc.z * ft.z, acc.w * ft.w);
    reinterpret_cast<float4*>(g_LfP + (size_t)row * FDIM)[lane] = lp;
    reinterpret_cast<float4*>(g_P   + (size_t)row * FDIM)[lane] = pp;
}

__global__ __launch_bounds__(256)
void spmm2_csr_kernel() {
    int row = blockIdx.x * (blockDim.x >> 5) + (threadIdx.x >> 5);
    if (row >= NNODES) return;
    int lane = threadIdx.x & 31;
    int beg = g_rowptr[row];
    int end = g_rowptr[row + 1];

    float4 acc = make_float4(0.f, 0.f, 0.f, 0.f);
    for (int base = beg; base < end; base += 32) {
        int cnt = min(32, end - base);
        int   mycol = 0;
        float myval = 0.f;
        if (lane < cnt) {
            int2 e = g_csr[base + lane];
            mycol = e.x;
            myval = __int_as_float(e.y);
        }
        #pragma unroll 4
        for (int j = 0; j < cnt; j++) {
            int   c = __shfl_sync(0xffffffffu, mycol, j);
            float v = __shfl_sync(0xffffffffu, myval, j);
            float4 x = reinterpret_cast<const float4*>(g_P + (size_t)c * FDIM)[lane];
            acc.x = fmaf(v, x.x, acc.x);
            acc.y = fmaf(v, x.y, acc.y);
            acc.z = fmaf(v, x.z, acc.z);
            acc.w = fmaf(v, x.w, acc.w);
        }
    }
    reinterpret_cast<float4*>(g_Li + (size_t)row * FDIM)[lane] = acc;
}

// ---------------------------------------------------------------------------
// Tensor-core GEMM via mma.sync m16n8k8 tf32 (arch-portable PTX):
//   out = [LfP ; Li] (N x 256) @ [W1 ; W2] (256 x 128) + (b1+b2)
//
// CTA: 256 thr = 8 warps. Warp tile M=32 x N=64 -> 4 row-groups x 2 col-groups
// cover 128x128 per CTA. K=256, A staged in 2 phases (LfP then Li).
// smem: Wt[n=128][k=256] stride 260 (tf32), As[128][128] stride 132 (tf32),
//       strides chosen so fragment loads hit all 32 banks (4*idx + tg).
// ---------------------------------------------------------------------------
#define WT_STRIDE 260
#define AS_STRIDE 132
#define OFF_WT 0
#define OFF_AS (128 * WT_STRIDE * 4)                  // 133120
#define OFF_BI (OFF_AS + 128 * AS_STRIDE * 4)         // 200704
#define SMEM_GEMM (OFF_BI + 512)                      // 201216

static __device__ __forceinline__ uint32_t f2tf32(float f) {
    uint32_t u;
    asm("cvt.rna.tf32.f32 %0, %1;" : "=r"(u) : "f"(f));
    return u;
}

static __device__ __forceinline__ void mma8(float* d, const uint32_t* a,
                                            uint32_t b0, uint32_t b1) {
    asm volatile(
        "mma.sync.aligned.m16n8k8.row.col.f32.tf32.tf32.f32 "
        "{%0,%1,%2,%3}, {%4,%5,%6,%7}, {%8,%9}, {%0,%1,%2,%3};"
        : "+f"(d[0]), "+f"(d[1]), "+f"(d[2]), "+f"(d[3])
        : "r"(a[0]), "r"(a[1]), "r"(a[2]), "r"(a[3]), "r"(b0), "r"(b1));
}

__global__ __launch_bounds__(256, 1)
void gemm_mma_kernel(const float* __restrict__ W1,
                     const float* __restrict__ b1,
                     const float* __restrict__ W2,
                     const float* __restrict__ b2,
                     float* __restrict__ out) {
    extern __shared__ char smem[];
    uint32_t* Wt   = reinterpret_cast<uint32_t*>(smem + OFF_WT);  // [128][260]
    uint32_t* As   = reinterpret_cast<uint32_t*>(smem + OFF_AS);  // [128][132]
    float*    bias = reinterpret_cast<float*>(smem + OFF_BI);

    const int tid  = threadIdx.x;
    const int w    = tid >> 5;
    const int lane = tid & 31;
    const int tg   = lane & 3;    // thread-in-group (k within frag)
    const int gid  = lane >> 2;   // group id (row/col within frag)
    const int wm   = w & 3;       // row-group
    const int colg = w >> 2;      // col-group
    const int row0 = blockIdx.x * 128;

    // ---- stage Wt[n][k] = tf32(W[k][n]), k<128 from W1, else W2 ----
    #pragma unroll
    for (int it = 0; it < 32; it++) {
        int wt = it * 8 + w;                 // 0..255 warp-tasks
        int k0 = (wt >> 2) * 4;              // 0..252 step 4
        int n  = (wt & 3) * 32 + lane;       // 0..127
        const float* Wsrc = (k0 < 128) ? (W1 + (size_t)k0 * 128)
                                       : (W2 + (size_t)(k0 - 128) * 128);
        uint4 st;
        st.x = f2tf32(Wsrc[0 * 128 + n]);
        st.y = f2tf32(Wsrc[1 * 128 + n]);
        st.z = f2tf32(Wsrc[2 * 128 + n]);
        st.w = f2tf32(Wsrc[3 * 128 + n]);
        *reinterpret_cast<uint4*>(Wt + n * WT_STRIDE + k0) = st;
    }
    if (tid < 128) bias[tid] = b1[tid] + b2[tid];

    float acc[2][8][4];
    #pragma unroll
    for (int s = 0; s < 2; s++)
        #pragma unroll
        for (int nt = 0; nt < 8; nt++)
            #pragma unroll
            for (int q = 0; q < 4; q++) acc[s][nt][q] = 0.f;

    #pragma unroll
    for (int phase = 0; phase < 2; phase++) {
        const float* src = phase ? g_Li : g_LfP;
        __syncthreads();   // Wt visible (phase 0) / prior mma reads done (phase 1)

        // ---- stage As[r][0..127] = tf32(src row) ----
        #pragma unroll
        for (int it = 0; it < 16; it++) {
            int idx = it * 256 + tid;
            int r = idx >> 5;
            int j = idx & 31;
            int row = row0 + r;
            if (row >= NNODES) row = NNODES - 1;
            float4 v = reinterpret_cast<const float4*>(src + (size_t)row * FDIM)[j];
            uint4 st = make_uint4(f2tf32(v.x), f2tf32(v.y), f2tf32(v.z), f2tf32(v.w));
            *reinterpret_cast<uint4*>(As + r * AS_STRIDE + j * 4) = st;
        }
        __syncthreads();

        const int kg0 = phase * 128;
        #pragma unroll 2
        for (int kb = 0; kb < 128; kb += 8) {
            uint32_t a[2][4];
            #pragma unroll
            for (int sub = 0; sub < 2; sub++) {
                int rb = wm * 32 + sub * 16 + gid;
                a[sub][0] = As[rb * AS_STRIDE + kb + tg];
                a[sub][1] = As[(rb + 8) * AS_STRIDE + kb + tg];
                a[sub][2] = As[rb * AS_STRIDE + kb + 4 + tg];
                a[sub][3] = As[(rb + 8) * AS_STRIDE + kb + 4 + tg];
            }
            #pragma unroll
            for (int nt = 0; nt < 8; nt++) {
                int n = colg * 64 + nt * 8 + gid;
                uint32_t b0 = Wt[n * WT_STRIDE + kg0 + kb + tg];
                uint32_t b1 = Wt[n * WT_STRIDE + kg0 + kb + 4 + tg];
                mma8(acc[0][nt], a[0], b0, b1);
                mma8(acc[1][nt], a[1], b0, b1);
            }
        }
    }

    // ---- epilogue: add bias, float2 stores ----
    #pragma unroll
    for (int sub = 0; sub < 2; sub++) {
        int r0 = row0 + wm * 32 + sub * 16 + gid;
        #pragma unroll
        for (int nt = 0; nt < 8; nt++) {
            int c = colg * 64 + nt * 8 + tg * 2;
            float bx = bias[c], by = bias[c + 1];
            if (r0 < NNODES) {
                float2 o = make_float2(acc[sub][nt][0] + bx, acc[sub][nt][1] + by);
                *reinterpret_cast<float2*>(out + (size_t)r0 * FDIM + c) = o;
            }
            if (r0 + 8 < NNODES) {
                float2 o = make_float2(acc[sub][nt][2] + bx, acc[sub][nt][3] + by);
                *reinterpret_cast<float2*>(out + (size_t)(r0 + 8) * FDIM + c) = o;
            }
        }
    }
}

// ---------------------------------------------------------------------------
extern "C" void kernel_launch(void* const* d_in, const int* in_sizes, int n_in,
                              void* d_out, int out_size) {
    const float* feat = (const float*)d_in[0];
    const float* eval = (const float*)d_in[1];
    const float* W1   = (const float*)d_in[2];
    const float* b1   = (const float*)d_in[3];
    const float* W2   = (const float*)d_in[4];
    const float* b2   = (const float*)d_in[5];
    const int*   erow = (const int*)d_in[6];
    const int*   ecol = (const int*)d_in[7];
    float*       out  = (float*)d_out;

    const int nnz = in_sizes[1];

    // CSR build
    zero_counts_kernel<<<(NNODES + 255) / 256, 256>>>();
    hist_kernel<<<(nnz + 255) / 256, 256>>>(erow, nnz);
    scan_kernel<<<1, 1024>>>();
    scatter_kernel<<<(nnz + 255) / 256, 256>>>(eval, erow, ecol, nnz);

    // SpMM passes (warp per row)
    {
        int blocks = (NNODES + 7) / 8;
        spmm1_csr_kernel<<<blocks, 256>>>(feat);
        spmm2_csr_kernel<<<blocks, 256>>>();
    }

    // GEMM (mma.sync tf32)
    {
        cudaFuncSetAttribute(gemm_mma_kernel,
                             cudaFuncAttributeMaxDynamicSharedMemorySize,
                             SMEM_GEMM);
        int blocks = (NNODES + 127) / 128;
        gemm_mma_kernel<<<blocks, 256, SMEM_GEMM>>>(W1, b1, W2, b2, out);
    }
}

// round 6
// speedup vs baseline: 2.5430x; 1.5309x over previous
#include <cuda_runtime.h>
#include <cstdint>

#define NNODES 100000
#define FDIM   128
#define NTILES ((NNODES + 127) / 128)

// ---- device-global scratch (allocations forbidden) ----
__device__ float g_LfP[(size_t)NNODES * FDIM];   // Lf + feat   (GEMM A, k 0..127)
__device__ float g_P  [(size_t)NNODES * FDIM];   // Lf * feat   (spmm2 input)
__device__ float g_Li [(size_t)NNODES * FDIM];   // A @ P       (GEMM A, k 128..255)
__device__ int   g_rowcnt[NNODES];
__device__ int   g_rowptr[NNODES + 1];
__device__ int   g_rowcur[NNODES];
__device__ int2  g_csr[1600000 + 1024];          // (col, float_bits(val)) packed

#define SCAN_B 1024
#define SCAN_G ((NNODES + SCAN_B - 1) / SCAN_B)  // 98
__device__ int g_bsum[SCAN_G];

// ---------------------------------------------------------------------------
// CSR build: zero counts -> histogram -> 3-stage scan -> scatter
// ---------------------------------------------------------------------------
__global__ void zero_counts_kernel() {
    int i = blockIdx.x * blockDim.x + threadIdx.x;
    if (i < NNODES) g_rowcnt[i] = 0;
}

__global__ void hist_kernel(const int* __restrict__ erow, int nnz) {
    int i = (blockIdx.x * blockDim.x + threadIdx.x) * 4;
    if (i + 3 < nnz) {
        int4 r = *reinterpret_cast<const int4*>(erow + i);
        atomicAdd(&g_rowcnt[r.x], 1);
        atomicAdd(&g_rowcnt[r.y], 1);
        atomicAdd(&g_rowcnt[r.z], 1);
        atomicAdd(&g_rowcnt[r.w], 1);
    } else {
        for (int j = i; j < nnz; j++) atomicAdd(&g_rowcnt[erow[j]], 1);
    }
}

// scan stage 1: per-block sums of 1024-wide chunks
__global__ __launch_bounds__(SCAN_B)
void scan_partial_kernel() {
    __shared__ int s[SCAN_B];
    int tid = threadIdx.x;
    int i = blockIdx.x * SCAN_B + tid;
    s[tid] = (i < NNODES) ? g_rowcnt[i] : 0;
    __syncthreads();
    for (int off = SCAN_B >> 1; off > 0; off >>= 1) {
        if (tid < off) s[tid] += s[tid + off];
        __syncthreads();
    }
    if (tid == 0) g_bsum[blockIdx.x] = s[0];
}

// scan stage 2: exclusive scan of the 98 block sums (1 tiny block)
__global__ __launch_bounds__(128, 1)
void scan_bsum_kernel() {
    __shared__ int s[128];
    int tid = threadIdx.x;
    int v = (tid < SCAN_G) ? g_bsum[tid] : 0;
    s[tid] = v;
    __syncthreads();
    for (int off = 1; off < 128; off <<= 1) {
        int t = (tid >= off) ? s[tid - off] : 0;
        __syncthreads();
        s[tid] += t;
        __syncthreads();
    }
    if (tid < SCAN_G) g_bsum[tid] = s[tid] - v;   // exclusive
}

// scan stage 3: block-local exclusive scan + block offset
__global__ __launch_bounds__(SCAN_B)
void scan_final_kernel() {
    __shared__ int s[SCAN_B];
    int tid = threadIdx.x;
    int i = blockIdx.x * SCAN_B + tid;
    int v = (i < NNODES) ? g_rowcnt[i] : 0;
    s[tid] = v;
    __syncthreads();
    for (int off = 1; off < SCAN_B; off <<= 1) {
        int t = (tid >= off) ? s[tid - off] : 0;
        __syncthreads();
        s[tid] += t;
        __syncthreads();
    }
    int excl = s[tid] - v + g_bsum[blockIdx.x];
    if (i < NNODES) {
        g_rowptr[i] = excl;
        g_rowcur[i] = excl;
        if (i == NNODES - 1) g_rowptr[NNODES] = excl + v;
    }
}

__global__ void scatter_kernel(const float* __restrict__ eval,
                               const int*   __restrict__ erow,
                               const int*   __restrict__ ecol,
                               int nnz) {
    int i = (blockIdx.x * blockDim.x + threadIdx.x) * 4;
    if (i + 3 < nnz) {
        int4   r = *reinterpret_cast<const int4*>(erow + i);
        int4   c = *reinterpret_cast<const int4*>(ecol + i);
        float4 v = *reinterpret_cast<const float4*>(eval + i);
        int p0 = atomicAdd(&g_rowcur[r.x], 1);
        int p1 = atomicAdd(&g_rowcur[r.y], 1);
        int p2 = atomicAdd(&g_rowcur[r.z], 1);
        int p3 = atomicAdd(&g_rowcur[r.w], 1);
        g_csr[p0] = make_int2(c.x, __float_as_int(v.x));
        g_csr[p1] = make_int2(c.y, __float_as_int(v.y));
        g_csr[p2] = make_int2(c.z, __float_as_int(v.z));
        g_csr[p3] = make_int2(c.w, __float_as_int(v.w));
    } else {
        for (int j = i; j < nnz; j++) {
            int pos = atomicAdd(&g_rowcur[erow[j]], 1);
            g_csr[pos] = make_int2(ecol[j], __float_as_int(eval[j]));
        }
    }
}

// ---------------------------------------------------------------------------
// SpMM-CSR, warp per row. Register accumulate, plain stores.
// ---------------------------------------------------------------------------
__global__ __launch_bounds__(256)
void spmm1_csr_kernel(const float* __restrict__ feat) {
    int row = blockIdx.x * (blockDim.x >> 5) + (threadIdx.x >> 5);
    if (row >= NNODES) return;
    int lane = threadIdx.x & 31;
    int beg = g_rowptr[row];
    int end = g_rowptr[row + 1];

    float4 acc = make_float4(0.f, 0.f, 0.f, 0.f);
    for (int base = beg; base < end; base += 32) {
        int cnt = min(32, end - base);
        int   mycol = 0;
        float myval = 0.f;
        if (lane < cnt) {
            int2 e = g_csr[base + lane];
            mycol = e.x;
            myval = __int_as_float(e.y);
        }
        #pragma unroll 8
        for (int j = 0; j < cnt; j++) {
            int   c = __shfl_sync(0xffffffffu, mycol, j);
            float v = __shfl_sync(0xffffffffu, myval, j);
            float4 x = reinterpret_cast<const float4*>(feat + (size_t)c * FDIM)[lane];
            acc.x = fmaf(v, x.x, acc.x);
            acc.y = fmaf(v, x.y, acc.y);
            acc.z = fmaf(v, x.z, acc.z);
            acc.w = fmaf(v, x.w, acc.w);
        }
    }
    float4 ft = reinterpret_cast<const float4*>(feat + (size_t)row * FDIM)[lane];
    float4 lp = make_float4(acc.x + ft.x, acc.y + ft.y, acc.z + ft.z, acc.w + ft.w);
    float4 pp = make_float4(acc.x * ft.x, acc.y * ft.y, acc.z * ft.z, acc.w * ft.w);
    reinterpret_cast<float4*>(g_LfP + (size_t)row * FDIM)[lane] = lp;
    reinterpret_cast<float4*>(g_P   + (size_t)row * FDIM)[lane] = pp;
}

__global__ __launch_bounds__(256)
void spmm2_csr_kernel() {
    int row = blockIdx.x * (blockDim.x >> 5) + (threadIdx.x >> 5);
    if (row >= NNODES) return;
    int lane = threadIdx.x & 31;
    int beg = g_rowptr[row];
    int end = g_rowptr[row + 1];

    float4 acc = make_float4(0.f, 0.f, 0.f, 0.f);
    for (int base = beg; base < end; base += 32) {
        int cnt = min(32, end - base);
        int   mycol = 0;
        float myval = 0.f;
        if (lane < cnt) {
            int2 e = g_csr[base + lane];
            mycol = e.x;
            myval = __int_as_float(e.y);
        }
        #pragma unroll 8
        for (int j = 0; j < cnt; j++) {
            int   c = __shfl_sync(0xffffffffu, mycol, j);
            float v = __shfl_sync(0xffffffffu, myval, j);
            float4 x = reinterpret_cast<const float4*>(g_P + (size_t)c * FDIM)[lane];
            acc.x = fmaf(v, x.x, acc.x);
            acc.y = fmaf(v, x.y, acc.y);
            acc.z = fmaf(v, x.z, acc.z);
            acc.w = fmaf(v, x.w, acc.w);
        }
    }
    reinterpret_cast<float4*>(g_Li + (size_t)row * FDIM)[lane] = acc;
}

// ---------------------------------------------------------------------------
// Persistent tensor-core GEMM (mma.sync m16n8k8 tf32):
//   out = [LfP ; Li] (N x 256) @ [W1 ; W2] (256 x 128) + (b1+b2)
// grid = 148 CTAs; W converted/staged ONCE per CTA, then loop over row tiles.
// ---------------------------------------------------------------------------
#define WT_STRIDE 260
#define AS_STRIDE 132
#define OFF_WT 0
#define OFF_AS (128 * WT_STRIDE * 4)                  // 133120
#define OFF_BI (OFF_AS + 128 * AS_STRIDE * 4)         // 200704
#define SMEM_GEMM (OFF_BI + 512)                      // 201216

static __device__ __forceinline__ uint32_t f2tf32(float f) {
    uint32_t u;
    asm("cvt.rna.tf32.f32 %0, %1;" : "=r"(u) : "f"(f));
    return u;
}

static __device__ __forceinline__ void mma8(float* d, const uint32_t* a,
                                            uint32_t b0, uint32_t b1) {
    asm volatile(
        "mma.sync.aligned.m16n8k8.row.col.f32.tf32.tf32.f32 "
        "{%0,%1,%2,%3}, {%4,%5,%6,%7}, {%8,%9}, {%0,%1,%2,%3};"
        : "+f"(d[0]), "+f"(d[1]), "+f"(d[2]), "+f"(d[3])
        : "r"(a[0]), "r"(a[1]), "r"(a[2]), "r"(a[3]), "r"(b0), "r"(b1));
}

__global__ __launch_bounds__(256, 1)
void gemm_mma_kernel(const float* __restrict__ W1,
                     const float* __restrict__ b1,
                     const float* __restrict__ W2,
                     const float* __restrict__ b2,
                     float* __restrict__ out) {
    extern __shared__ char smem[];
    uint32_t* Wt   = reinterpret_cast<uint32_t*>(smem + OFF_WT);  // [128][260]
    uint32_t* As   = reinterpret_cast<uint32_t*>(smem + OFF_AS);  // [128][132]
    float*    bias = reinterpret_cast<float*>(smem + OFF_BI);

    const int tid  = threadIdx.x;
    const int w    = tid >> 5;
    const int lane = tid & 31;
    const int tg   = lane & 3;    // k within frag
    const int gid  = lane >> 2;   // row/col within frag
    const int wm   = w & 3;       // row-group
    const int colg = w >> 2;      // col-group

    // ---- stage Wt[n][k] = tf32(W[k][n]) ONCE ----
    #pragma unroll
    for (int it = 0; it < 32; it++) {
        int wt = it * 8 + w;                 // 0..255 warp-tasks
        int k0 = (wt >> 2) * 4;              // 0..252 step 4
        int n  = (wt & 3) * 32 + lane;       // 0..127
        const float* Wsrc = (k0 < 128) ? (W1 + (size_t)k0 * 128)
                                       : (W2 + (size_t)(k0 - 128) * 128);
        uint4 st;
        st.x = f2tf32(Wsrc[0 * 128 + n]);
        st.y = f2tf32(Wsrc[1 * 128 + n]);
        st.z = f2tf32(Wsrc[2 * 128 + n]);
        st.w = f2tf32(Wsrc[3 * 128 + n]);
        *reinterpret_cast<uint4*>(Wt + n * WT_STRIDE + k0) = st;
    }
    if (tid < 128) bias[tid] = b1[tid] + b2[tid];

    for (int tile = blockIdx.x; tile < NTILES; tile += gridDim.x) {
        const int row0 = tile * 128;

        float acc[2][8][4];
        #pragma unroll
        for (int s = 0; s < 2; s++)
            #pragma unroll
            for (int nt = 0; nt < 8; nt++)
                #pragma unroll
                for (int q = 0; q < 4; q++) acc[s][nt][q] = 0.f;

        #pragma unroll
        for (int phase = 0; phase < 2; phase++) {
            const float* src = phase ? g_Li : g_LfP;
            __syncthreads();   // Wt ready / As free (prior MMAs & staging done)

            // ---- stage As[r][0..127] = tf32(src row) ----
            #pragma unroll
            for (int it = 0; it < 16; it++) {
                int idx = it * 256 + tid;
                int r = idx >> 5;
                int j = idx & 31;
                int row = row0 + r;
                if (row >= NNODES) row = NNODES - 1;
                float4 v = reinterpret_cast<const float4*>(src + (size_t)row * FDIM)[j];
                uint4 st = make_uint4(f2tf32(v.x), f2tf32(v.y), f2tf32(v.z), f2tf32(v.w));
                *reinterpret_cast<uint4*>(As + r * AS_STRIDE + j * 4) = st;
            }
            __syncthreads();

            const int kg0 = phase * 128;
            #pragma unroll 2
            for (int kb = 0; kb < 128; kb += 8) {
                uint32_t a[2][4];
                #pragma unroll
                for (int sub = 0; sub < 2; sub++) {
                    int rb = wm * 32 + sub * 16 + gid;
                    a[sub][0] = As[rb * AS_STRIDE + kb + tg];
                    a[sub][1] = As[(rb + 8) * AS_STRIDE + kb + tg];
                    a[sub][2] = As[rb * AS_STRIDE + kb + 4 + tg];
                    a[sub][3] = As[(rb + 8) * AS_STRIDE + kb + 4 + tg];
                }
                #pragma unroll
                for (int nt = 0; nt < 8; nt++) {
                    int n = colg * 64 + nt * 8 + gid;
                    uint32_t b0 = Wt[n * WT_STRIDE + kg0 + kb + tg];
                    uint32_t b1 = Wt[n * WT_STRIDE + kg0 + kb + 4 + tg];
                    mma8(acc[0][nt], a[0], b0, b1);
                    mma8(acc[1][nt], a[1], b0, b1);
                }
            }
        }

        // ---- epilogue: add bias, float2 stores ----
        #pragma unroll
        for (int sub = 0; sub < 2; sub++) {
            int r0 = row0 + wm * 32 + sub * 16 + gid;
            #pragma unroll
            for (int nt = 0; nt < 8; nt++) {
                int c = colg * 64 + nt * 8 + tg * 2;
                float bx = bias[c], by = bias[c + 1];
                if (r0 < NNODES) {
                    float2 o = make_float2(acc[sub][nt][0] + bx, acc[sub][nt][1] + by);
                    *reinterpret_cast<float2*>(out + (size_t)r0 * FDIM + c) = o;
                }
                if (r0 + 8 < NNODES) {
                    float2 o = make_float2(acc[sub][nt][2] + bx, acc[sub][nt][3] + by);
                    *reinterpret_cast<float2*>(out + (size_t)(r0 + 8) * FDIM + c) = o;
                }
            }
        }
    }
}

// ---------------------------------------------------------------------------
extern "C" void kernel_launch(void* const* d_in, const int* in_sizes, int n_in,
                              void* d_out, int out_size) {
    const float* feat = (const float*)d_in[0];
    const float* eval = (const float*)d_in[1];
    const float* W1   = (const float*)d_in[2];
    const float* b1   = (const float*)d_in[3];
    const float* W2   = (const float*)d_in[4];
    const float* b2   = (const float*)d_in[5];
    const int*   erow = (const int*)d_in[6];
    const int*   ecol = (const int*)d_in[7];
    float*       out  = (float*)d_out;

    const int nnz = in_sizes[1];

    // CSR build
    zero_counts_kernel<<<(NNODES + 255) / 256, 256>>>();
    hist_kernel<<<(nnz / 4 + 255) / 256, 256>>>(erow, nnz);
    scan_partial_kernel<<<SCAN_G, SCAN_B>>>();
    scan_bsum_kernel<<<1, 128>>>();
    scan_final_kernel<<<SCAN_G, SCAN_B>>>();
    scatter_kernel<<<(nnz / 4 + 255) / 256, 256>>>(eval, erow, ecol, nnz);

    // SpMM passes (warp per row)
    {
        int blocks = (NNODES + 7) / 8;
        spmm1_csr_kernel<<<blocks, 256>>>(feat);
        spmm2_csr_kernel<<<blocks, 256>>>();
    }

    // GEMM (persistent, mma.sync tf32)
    {
        cudaFuncSetAttribute(gemm_mma_kernel,
                             cudaFuncAttributeMaxDynamicSharedMemorySize,
                             SMEM_GEMM);
        gemm_mma_kernel<<<148, 256, SMEM_GEMM>>>(W1, b1, W2, b2, out);
    }
}